// round 17
// baseline (speedup 1.0000x reference)
#include <cuda_runtime.h>
#include <cstdint>

#define B_DIM 32
#define S_LEN 2048
#define I_DIM 256
#define H_DIM 256
#define CLN 4                             // recurrence cluster size

// ---------------------------------------------------------------------------
// helpers
// ---------------------------------------------------------------------------
__device__ __forceinline__ unsigned long long ffma2(unsigned long long a,
                                                    unsigned long long b,
                                                    unsigned long long c) {
    unsigned long long d;
    asm("fma.rn.f32x2 %0, %1, %2, %3;" : "=l"(d) : "l"(a), "l"(b), "l"(c));
    return d;
}
__device__ __forceinline__ unsigned long long pack2(float x, float y) {
    unsigned long long d;
    asm("mov.b64 %0, {%1, %2};" : "=l"(d) : "f"(x), "f"(y));
    return d;
}
__device__ __forceinline__ float2 unpack2(unsigned long long v) {
    float2 r;
    asm("mov.b64 {%0, %1}, %2;" : "=f"(r.x), "=f"(r.y) : "l"(v));
    return r;
}
__device__ __forceinline__ uint32_t smem_u32(const void* p) {
    uint32_t a;
    asm("{ .reg .u64 t; cvta.to.shared.u64 t, %1; cvt.u32.u64 %0, t; }"
        : "=r"(a) : "l"(p));
    return a;
}
__device__ __forceinline__ uint32_t mapa_u32(uint32_t a, uint32_t rank) {
    uint32_t d;
    asm("mapa.shared::cluster.u32 %0, %1, %2;" : "=r"(d) : "r"(a), "r"(rank));
    return d;
}
__device__ __forceinline__ void mbar_init(uint32_t mbar, uint32_t count) {
    asm volatile("mbarrier.init.shared.b64 [%0], %1;" :: "r"(mbar), "r"(count) : "memory");
}
__device__ __forceinline__ void mbar_expect_tx(uint32_t mbar, uint32_t bytes) {
    asm volatile("mbarrier.arrive.expect_tx.shared.b64 _, [%0], %1;"
                 :: "r"(mbar), "r"(bytes) : "memory");
}
__device__ __forceinline__ void mbar_wait(uint32_t mbar, uint32_t parity) {
    asm volatile(
        "{\n\t.reg .pred P;\n\t"
        "WL%=:\n\t"
        "mbarrier.try_wait.parity.acquire.cta.shared::cta.b64 P, [%0], %1, 0x989680;\n\t"
        "@!P bra WL%=;\n\t}"
        :: "r"(mbar), "r"(parity) : "memory");
}
__device__ __forceinline__ void st_async_f32(uint32_t raddr, float v, uint32_t rmbar) {
    asm volatile(
        "st.async.shared::cluster.mbarrier::complete_tx::bytes.f32 [%0], %1, [%2];"
        :: "r"(raddr), "f"(v), "r"(rmbar) : "memory");
}
__device__ __forceinline__ float tanh_fast(float x) {
    float r;
    asm("tanh.approx.f32 %0, %1;" : "=f"(r) : "f"(x));
    return r;
}

// ---------------------------------------------------------------------------
// Kernel 1: xw[b,s,h] = x[b,s,:] . Wx_w[h,:] + Wx_b[h]  (into outputs region)
// Proven standalone GEMM (~220us on 148 SMs, occupancy 2).
// ---------------------------------------------------------------------------
__global__ __launch_bounds__(256, 2)
void xw_gemm_kernel(const float* __restrict__ A, const float* __restrict__ W,
                    const float* __restrict__ bias, float* __restrict__ C) {
    __shared__ __align__(16) float As[16][128];
    __shared__ __align__(16) float Bs[16][128];

    const int tid = threadIdx.x;
    const int tx = tid & 15;
    const int ty = tid >> 4;
    const long bm = (long)blockIdx.x * 128;
    const long bn = (long)blockIdx.y * 128;

    const float* Ab = A + bm * I_DIM;
    const float* Wb = W + bn * I_DIM;

    unsigned long long acc[8][4];
#pragma unroll
    for (int i = 0; i < 8; i++)
#pragma unroll
        for (int j = 0; j < 4; j++) acc[i][j] = 0ull;

    for (int k0 = 0; k0 < I_DIM; k0 += 16) {
#pragma unroll
        for (int f = tid; f < 512; f += 256) {
            int row = f >> 2, kq = f & 3;
            float4 va = *(const float4*)(Ab + (long)row * I_DIM + k0 + kq * 4);
            As[kq * 4 + 0][row] = va.x; As[kq * 4 + 1][row] = va.y;
            As[kq * 4 + 2][row] = va.z; As[kq * 4 + 3][row] = va.w;
            float4 vw = *(const float4*)(Wb + (long)row * I_DIM + k0 + kq * 4);
            Bs[kq * 4 + 0][row] = vw.x; Bs[kq * 4 + 1][row] = vw.y;
            Bs[kq * 4 + 2][row] = vw.z; Bs[kq * 4 + 3][row] = vw.w;
        }
        __syncthreads();
#pragma unroll
        for (int k = 0; k < 16; k++) {
            const float4* As4 = (const float4*)&As[k][0];
            const ulonglong2* Bs2 = (const ulonglong2*)&Bs[k][0];
            float4 a0 = As4[ty * 2], a1 = As4[ty * 2 + 1];
            ulonglong2 bA = Bs2[tx * 2], bB = Bs2[tx * 2 + 1];
            unsigned long long bp[4] = {bA.x, bA.y, bB.x, bB.y};
            float av[8] = {a0.x, a0.y, a0.z, a0.w, a1.x, a1.y, a1.z, a1.w};
#pragma unroll
            for (int i = 0; i < 8; i++) {
                unsigned long long ap = pack2(av[i], av[i]);
#pragma unroll
                for (int j = 0; j < 4; j++) acc[i][j] = ffma2(ap, bp[j], acc[i][j]);
            }
        }
        __syncthreads();
    }

    float bv[8];
#pragma unroll
    for (int j = 0; j < 8; j++) bv[j] = bias[bn + tx * 8 + j];
#pragma unroll
    for (int i = 0; i < 8; i++) {
        long m = bm + ty * 8 + i;
        float* Crow = C + m * (long)H_DIM + bn + tx * 8;
        float2 c0 = unpack2(acc[i][0]), c1 = unpack2(acc[i][1]);
        float2 c2 = unpack2(acc[i][2]), c3 = unpack2(acc[i][3]);
        *(float4*)(Crow)     = make_float4(c0.x + bv[0], c0.y + bv[1], c1.x + bv[2], c1.y + bv[3]);
        *(float4*)(Crow + 4) = make_float4(c2.x + bv[4], c2.y + bv[5], c3.x + bv[6], c3.y + bv[7]);
    }
}

// ---------------------------------------------------------------------------
// Kernel 2: recurrence, 4-CTA cluster per batch row (no flags, xw complete).
// CTA rank r owns outputs [64r,64r+64) and h quarter [64r,64r+64).
// Thread t computes P = Wh[t][64r:64r+64] . h_local (16 broadcast LDS.128 +
// 32 ffma2, no shfl). Non-local threads (t>>6 != r) ship P to owner CTA's
// pbuf[b][t&63][r] (192 msgs x 4B = 768B expect_tx). Local threads wait,
// add 3 remote partials (own slot stays 0; own P in register), tanh, store
// h locally (h never crosses CTAs) and write the output.
// ---------------------------------------------------------------------------
__global__ __launch_bounds__(256, 1) __cluster_dims__(CLN, 1, 1)
void srnn_recur_kernel(const float* __restrict__ Wh, float* __restrict__ out) {
    __shared__ __align__(16) float hS[2][64];        // [buf][jl] my h quarter
    __shared__ __align__(16) float pbuf[2][64][4];   // [buf][jl][src]
    __shared__ __align__(8) unsigned long long mbarp[2];

    const int rank = blockIdx.x;          // 0..3
    const int row  = blockIdx.y;
    const int t    = threadIdx.x;
    const int jl   = t & 63;              // index within a quarter
    const int dstRank = t >> 6;           // owner CTA of output t
    const bool isLocal = (dstRank == rank);

    // --- weights: Wh row = output t, k in my h quarter [64r, 64r+64)
    unsigned long long w[32];
    {
        const float* wr = Wh + (long)t * H_DIM + rank * 64;
#pragma unroll
        for (int u = 0; u < 16; u++) {
            ulonglong2 a = *(const ulonglong2*)(wr + u * 4);
            w[2 * u]     = a.x;
            w[2 * u + 1] = a.y;
        }
    }

    const uint32_t mb0 = smem_u32(&mbarp[0]);
    const uint32_t mb1 = smem_u32(&mbarp[1]);

    if (t == 0) {
        mbar_init(mb0, 1);
        mbar_init(mb1, 1);
        mbar_expect_tx(mb0, 768);         // 192 msgs x 4B per step
        mbar_expect_tx(mb1, 768);
    }
    if (t < 64) hS[0][t] = 0.0f;          // h0 = 0 (my quarter)
    for (int i = t; i < 2 * 64 * 4; i += 256) ((float*)pbuf)[i] = 0.0f;
    __syncthreads();
    asm volatile("barrier.cluster.arrive.aligned;" ::: "memory");
    asm volatile("barrier.cluster.wait.aligned;" ::: "memory");

    // shipper destinations: owner CTA's pbuf[b][jl][rank]
    const uint32_t dA0 = mapa_u32(smem_u32(&pbuf[0][jl][rank]), dstRank);
    const uint32_t dA1 = mapa_u32(smem_u32(&pbuf[1][jl][rank]), dstRank);
    const uint32_t dm0 = mapa_u32(mb0, dstRank);
    const uint32_t dm1 = mapa_u32(mb1, dstRank);

    float* xwp = out + (long)row * S_LEN * H_DIM + t;   // my output column = t
    float xw_next = isLocal ? xwp[0] : 0.0f;

    for (int step = 0; step < S_LEN; step++) {
        const int b = step & 1;

        // ---- 64-k dot from local h quarter (16 broadcast LDS.128) ----
        const ulonglong2* h2 = (const ulonglong2*)&hS[b][0];
        unsigned long long a0 = 0ull, a1 = 0ull, a2 = 0ull, a3 = 0ull;
#pragma unroll
        for (int u = 0; u < 16; u += 2) {
            ulonglong2 hv0 = h2[u], hv1 = h2[u + 1];
            a0 = ffma2(hv0.x, w[2 * u], a0);
            a1 = ffma2(hv0.y, w[2 * u + 1], a1);
            a2 = ffma2(hv1.x, w[2 * u + 2], a2);
            a3 = ffma2(hv1.y, w[2 * u + 3], a3);
        }
        float2 f0 = unpack2(a0), f1 = unpack2(a1);
        float2 f2 = unpack2(a2), f3 = unpack2(a3);
        float S = ((f0.x + f0.y) + (f1.x + f1.y)) +
                  ((f2.x + f2.y) + (f3.x + f3.y));

        if (!isLocal) {
            // ship my partial to the owner CTA
            st_async_f32(b ? dA1 : dA0, S, b ? dm1 : dm0);
        } else {
            // finish my output: wait for 3 remote partials (own slot is 0)
            mbar_wait(b ? mb1 : mb0, (step >> 1) & 1);
            if (t == rank * 64) mbar_expect_tx(b ? mb1 : mb0, 768);

            float4 pp = *(const float4*)&pbuf[b][jl][0];
            float v = tanh_fast(S + (pp.x + pp.y) + (pp.z + pp.w) + xw_next);
            hS[b ^ 1][jl] = v;                        // h(step+1), local only
            xwp[(long)step * H_DIM] = v;              // in-place output
            if (step == S_LEN - 1)
                out[(long)B_DIM * S_LEN * H_DIM + (long)row * H_DIM + t] = v;
            if (step + 1 < S_LEN)
                xw_next = xwp[(long)(step + 1) * H_DIM];
        }

        __syncthreads();                              // h(step+1) visible
    }

    asm volatile("barrier.cluster.arrive.aligned;" ::: "memory");
    asm volatile("barrier.cluster.wait.aligned;" ::: "memory");
}

// ---------------------------------------------------------------------------
// Launch: GEMM first (stream-ordered), then 4-CTA recurrence. No flags.
// ---------------------------------------------------------------------------
extern "C" void kernel_launch(void* const* d_in, const int* in_sizes, int n_in,
                              void* d_out, int out_size) {
    const float* x    = (const float*)d_in[0];  // [B,S,I]
    const float* Wx_w = (const float*)d_in[1];  // [H,I]
    const float* Wx_b = (const float*)d_in[2];  // [H]
    const float* Wh_w = (const float*)d_in[3];  // [H,H]
    float* out = (float*)d_out;                 // [B,S,H] ++ [B,H]

    dim3 g1((B_DIM * S_LEN) / 128, H_DIM / 128);
    xw_gemm_kernel<<<g1, 256>>>(x, Wx_w, Wx_b, out);

    dim3 g2(CLN, B_DIM);                        // 32 clusters x 4 CTAs
    srnn_recur_kernel<<<g2, 256>>>(Wh_w, out);
}